// round 6
// baseline (speedup 1.0000x reference)
#include <cuda_runtime.h>
#include <stdint.h>
#include <math.h>

// Problem constants (fixed by the dataset)
#define BB 8
#define NV 500000
#define NF 1000000
#define VSTRIDE 32            // padded row: 24 used floats + 8 pad = 128B line
#define NEPAD (6*NF + 8*NV)   // CSR capacity incl. per-vertex pad to multiple of 8

#define SCAN_CHUNK 1024
#define SCAN_NB ((NV + SCAN_CHUNK - 1)/SCAN_CHUNK)   // 489

// ---- device-global scratch (no cudaMalloc allowed) ----
// row NV is the dummy zero row (never written -> stays zero across replays)
__device__ __align__(128) float g_vt[(size_t)(NV+1)*VSTRIDE];  // [N+1][32]
__device__ int   g_deg[NV];              // true degree
__device__ int   g_off[NV+1];            // CSR offsets of PADDED degrees (multiples of 8)
__device__ int   g_cur[NV];              // fill cursors
__device__ __align__(16) int g_adj[NEPAD];  // CSR adjacency (tail of each segment = garbage, masked)
__device__ __align__(16) int g_fi[4*NF]; // faces as int4 (i,j,k,pad)
__device__ int   g_bsum[1024];           // scan block sums
__device__ int   g_is64;                 // faces dtype flag (1 = int64, 0 = int32)

// ---------------------------------------------------------------------------
// 1) vert (B,N,3) -> vt (N, 32-padded): element b*3+c.
//    Fused: zero g_deg; block 0 also runs the faces-dtype probe.
// ---------------------------------------------------------------------------
__global__ void k_transpose(const float* __restrict__ vert,
                            const int*   __restrict__ fprobe) {
    __shared__ float s[64*24];
    int n0 = blockIdx.x * 64;
    int t  = threadIdx.x;                 // 192 threads

    // fused dtype probe (block 0): int64 faces w/ values<500000 have all odd
    // 32-bit words zero; impossible for int32 data over 4096 random samples.
    if (blockIdx.x == 0) {
        __shared__ int any;
        if (t == 0) any = 0;
        __syncthreads();
        int bad = 0;
        for (int i = t; i < 4096; i += 192)
            if (fprobe[2*i + 1] != 0) bad = 1;
        if (bad) atomicOr(&any, 1);
        __syncthreads();
        if (t == 0) g_is64 = (any == 0);
    }

    int gi = blockIdx.x * 192 + t;        // fused degree zeroing
    if (gi < NV) g_deg[gi] = 0;

    int nrem = NV - n0; if (nrem > 64) nrem = 64;
    int cnt = nrem * 3;
    #pragma unroll
    for (int b = 0; b < 8; b++) {
        if (t < cnt) {
            int v = t / 3, c = t - v*3;
            s[v*24 + b*3 + c] = vert[(size_t)b*NV*3 + (size_t)n0*3 + t];
        }
    }
    __syncthreads();
    int tot = nrem * 24;
    for (int i = t; i < tot; i += 192) {
        int v = i / 24, e = i - v*24;
        g_vt[(size_t)(n0 + v)*VSTRIDE + e] = s[i];
    }
}

// ---------------------------------------------------------------------------
// 3) degree histogram + int4 face conversion (single faces pass)
// ---------------------------------------------------------------------------
__global__ void k_hist(const void* __restrict__ faces) {
    int f = blockIdx.x * blockDim.x + threadIdx.x;
    if (f >= NF) return;
    int i, j, k;
    if (g_is64) {
        const long long* p = (const long long*)faces + (size_t)f * 3;
        i = (int)p[0]; j = (int)p[1]; k = (int)p[2];
    } else {
        const int* p = (const int*)faces + (size_t)f * 3;
        i = p[0]; j = p[1]; k = p[2];
    }
    i = min(max(i, 0), NV - 1);
    j = min(max(j, 0), NV - 1);
    k = min(max(k, 0), NV - 1);
    *(int4*)&g_fi[(size_t)f*4] = make_int4(i, j, k, 0);
    atomicAdd(&g_deg[i], 2);
    atomicAdd(&g_deg[j], 2);
    atomicAdd(&g_deg[k], 2);
}

// ---------------------------------------------------------------------------
// 4) two-level exclusive scan over PADDED degrees ((deg+7)&~7)
// ---------------------------------------------------------------------------
__device__ __forceinline__ int pdeg_of(int i) {
    return (i < NV) ? ((g_deg[i] + 7) & ~7) : 0;
}

__global__ void k_scanA() {
    __shared__ int s[SCAN_CHUNK];
    int i = blockIdx.x * SCAN_CHUNK + threadIdx.x;
    s[threadIdx.x] = pdeg_of(i);
    __syncthreads();
    for (int d = SCAN_CHUNK/2; d > 0; d >>= 1) {
        if (threadIdx.x < d) s[threadIdx.x] += s[threadIdx.x + d];
        __syncthreads();
    }
    if (threadIdx.x == 0) g_bsum[blockIdx.x] = s[0];
}

__global__ void k_scanB() {
    __shared__ int s[512];
    int t = threadIdx.x;                  // 512 threads, SCAN_NB=489 entries
    int v = (t < SCAN_NB) ? g_bsum[t] : 0;
    s[t] = v;
    __syncthreads();
    for (int d = 1; d < 512; d <<= 1) {
        int x = (t >= d) ? s[t-d] : 0;
        __syncthreads();
        s[t] += x;
        __syncthreads();
    }
    if (t < SCAN_NB) g_bsum[t] = s[t] - v;       // exclusive
    if (t == 511)    g_off[NV] = s[511];         // total padded entries
}

__global__ void k_scanC() {
    __shared__ int s[SCAN_CHUNK];
    int t = threadIdx.x;
    int i = blockIdx.x * SCAN_CHUNK + t;
    int pd = pdeg_of(i);
    s[t] = pd;
    __syncthreads();
    for (int d = 1; d < SCAN_CHUNK; d <<= 1) {
        int x = (t >= d) ? s[t-d] : 0;
        __syncthreads();
        s[t] += x;
        __syncthreads();
    }
    int ex = s[t] - pd + g_bsum[blockIdx.x];
    if (i < NV) { g_off[i] = ex; g_cur[i] = ex; }
}

// ---------------------------------------------------------------------------
// 5) CSR fill: per face, append the 2 neighbors of each corner (int2 stores)
// ---------------------------------------------------------------------------
__global__ void k_fill() {
    int f = blockIdx.x * blockDim.x + threadIdx.x;
    if (f >= NF) return;
    int4 fc = *(const int4*)&g_fi[(size_t)f*4];
    int i = fc.x, j = fc.y, k = fc.z;
    int p;
    p = atomicAdd(&g_cur[i], 2); *(int2*)&g_adj[p] = make_int2(j, k);
    p = atomicAdd(&g_cur[j], 2); *(int2*)&g_adj[p] = make_int2(i, k);
    p = atomicAdd(&g_cur[k], 2); *(int2*)&g_adj[p] = make_int2(i, j);
}

// ---------------------------------------------------------------------------
// 6) gather + curvature + fused output transpose.
//    One warp per vertex, lane e<24 owns element b*3+c of the vt row.
//    Adjacency via uniform int4 loads (32B-aligned segments); final partial
//    group masked to the shared zero row NV (no pad writes needed).
//    Block (8 warps = 8 consecutive vertices) stages curvature in smem and
//    writes out[8][N] coalesced (32B per batch per block).
// ---------------------------------------------------------------------------
__global__ void k_gather(float* __restrict__ out) {
    __shared__ float sc[8][9];            // [warp][batch] (+pad col)
    int warp = threadIdx.x >> 5;
    int lane = threadIdx.x & 31;
    int gw   = blockIdx.x * 8 + warp;     // NV % 8 == 0

    int start = g_off[gw];
    int deg   = g_deg[gw];
    int fend  = start + (deg & ~7);       // full 8-groups
    int end   = start + deg;

    bool act = lane < 24;
    float own = 0.f, acc = 0.f;
    if (act) own = __ldg(&g_vt[(size_t)gw*VSTRIDE + lane]);

    int base = start;
    for (; base < fend; base += 8) {
        int4 q0 = __ldg((const int4*)&g_adj[base]);
        int4 q1 = __ldg((const int4*)&g_adj[base + 4]);
        if (act) {
            float a = __ldg(&g_vt[(size_t)q0.x*VSTRIDE + lane]);
            float b = __ldg(&g_vt[(size_t)q0.y*VSTRIDE + lane]);
            float c = __ldg(&g_vt[(size_t)q0.z*VSTRIDE + lane]);
            float d = __ldg(&g_vt[(size_t)q0.w*VSTRIDE + lane]);
            float e = __ldg(&g_vt[(size_t)q1.x*VSTRIDE + lane]);
            float f = __ldg(&g_vt[(size_t)q1.y*VSTRIDE + lane]);
            float g = __ldg(&g_vt[(size_t)q1.z*VSTRIDE + lane]);
            float h = __ldg(&g_vt[(size_t)q1.w*VSTRIDE + lane]);
            acc += ((a + b) + (c + d)) + ((e + f) + (g + h));
        }
    }
    if (base < end) {                      // masked tail (deg%8 in {2,4,6})
        int4 q0 = __ldg((const int4*)&g_adj[base]);
        int4 q1 = __ldg((const int4*)&g_adj[base + 4]);
        int i0 = (base + 0 < end) ? q0.x : NV;
        int i1 = (base + 1 < end) ? q0.y : NV;
        int i2 = (base + 2 < end) ? q0.z : NV;
        int i3 = (base + 3 < end) ? q0.w : NV;
        int i4 = (base + 4 < end) ? q1.x : NV;
        int i5 = (base + 5 < end) ? q1.y : NV;
        int i6 = (base + 6 < end) ? q1.z : NV;
        if (act) {
            float a = __ldg(&g_vt[(size_t)i0*VSTRIDE + lane]);
            float b = __ldg(&g_vt[(size_t)i1*VSTRIDE + lane]);
            float c = __ldg(&g_vt[(size_t)i2*VSTRIDE + lane]);
            float d = __ldg(&g_vt[(size_t)i3*VSTRIDE + lane]);
            float e = __ldg(&g_vt[(size_t)i4*VSTRIDE + lane]);
            float f = __ldg(&g_vt[(size_t)i5*VSTRIDE + lane]);
            float g = __ldg(&g_vt[(size_t)i6*VSTRIDE + lane]);
            acc += ((a + b) + (c + d)) + ((e + f) + g);
        }
    }

    float inv = 1.f / fmaxf((float)deg, 1.f);
    float lap = acc * inv - own;
    float sq  = lap * lap;
    float s1 = __shfl_down_sync(0xffffffffu, sq, 1);
    float s2 = __shfl_down_sync(0xffffffffu, sq, 2);
    float sum = sq + s1 + s2;
    if (act && (lane % 3) == 0)
        sc[warp][lane / 3] = sqrtf(sum);
    __syncthreads();

    // coalesced output: thread t<64 writes out[b*NV + blockIdx.x*8 + v]
    if (threadIdx.x < 64) {
        int b = threadIdx.x >> 3, v = threadIdx.x & 7;
        out[(size_t)b*NV + blockIdx.x*8 + v] = sc[v][b];
    }
}

// ---------------------------------------------------------------------------
extern "C" void kernel_launch(void* const* d_in, const int* in_sizes, int n_in,
                              void* d_out, int out_size) {
    const float* vert  = (const float*)d_in[0];   // (8, 500000, 3) f32
    const void*  faces = d_in[1];                 // (1000000, 3) i64 OR i32
    float* out = (float*)d_out;                   // (8, 500000) f32

    // 1) transpose vertices (+ fused probe + degree zeroing)
    k_transpose<<<(NV + 63) / 64, 192>>>(vert, (const int*)faces);
    // 3) degree histogram + int4 conversion
    k_hist<<<(NF + 255) / 256, 256>>>(faces);
    // 4) exclusive scan of padded degrees -> aligned CSR offsets
    k_scanA<<<SCAN_NB, SCAN_CHUNK>>>();
    k_scanB<<<1, 512>>>();
    k_scanC<<<SCAN_NB, SCAN_CHUNK>>>();
    // 5) CSR fill (int4 faces, int2 stores)
    k_fill<<<(NF + 255) / 256, 256>>>();
    // 6) gather + curvature + fused output transpose
    k_gather<<<NV / 8, 256>>>(out);
}